// round 11
// baseline (speedup 1.0000x reference)
#include <cuda_runtime.h>

#define NN   32768
#define EE   524288
#define BB   64
#define HIDN 128
#define NHEAD 4
#define DHEAD 32
#define NEG  0.2f

// ---- scratch (static device memory; no allocation) ----
__device__ float g_XL[NHEAD * NN * DHEAD];   // [H][N][D]
__device__ float g_XR[NHEAD * NN * DHEAD];   // [H][N][D]
__device__ float g_H[NN * HIDN];             // node activations [N][128]
__device__ int   g_deg[NN];
__device__ int   g_rp[NN];
__device__ int   g_cpack[EE];                // srcLocal | dstLocal<<16, CSR-sorted by dst
__device__ float g_feat[BB * 2 * HIDN];      // [B][mean(128) | max(128)]

// ---- packed fp32x2 FFMA2 helpers ----
__device__ __forceinline__ unsigned long long pk2(float x, float y) {
    unsigned long long r;
    asm("mov.b64 %0, {%1, %2};" : "=l"(r) : "f"(x), "f"(y));
    return r;
}
__device__ __forceinline__ float2 upk2(unsigned long long v) {
    float2 r;
    asm("mov.b64 {%0, %1}, %2;" : "=f"(r.x), "=f"(r.y) : "l"(v));
    return r;
}
__device__ __forceinline__ unsigned long long ffma2(
    unsigned long long a, unsigned long long b, unsigned long long c) {
    unsigned long long d;
    asm("fma.rn.f32x2 %0, %1, %2, %3;" : "=l"(d) : "l"(a), "l"(b), "l"(c));
    return d;
}

// ---- CSR build: one block per graph, counting sort entirely in smem ----
__global__ __launch_bounds__(512) void csr_build_k(
    const int* __restrict__ esrc, const int* __restrict__ edst)
{
    __shared__ int cnt[512];
    __shared__ int sc[512];
    __shared__ int wp[512];
    int g = blockIdx.x, t = threadIdx.x;
    int eb = g * 8192;
    cnt[t] = 0;
    __syncthreads();
#pragma unroll 1
    for (int it = 0; it < 16; ++it) {
        int d = edst[eb + it * 512 + t] & 511;
        atomicAdd(&cnt[d], 1);
    }
    __syncthreads();
    int d0 = cnt[t];
    int val = d0;
    sc[t] = val;
    __syncthreads();
    for (int off = 1; off < 512; off <<= 1) {
        int add = (t >= off) ? sc[t - off] : 0;
        __syncthreads();
        val += add;
        sc[t] = val;
        __syncthreads();
    }
    int rpx = val - d0;   // exclusive scan
    g_deg[g * 512 + t] = d0;
    g_rp[g * 512 + t] = eb + rpx;
    wp[t] = rpx;
    __syncthreads();
#pragma unroll 1
    for (int it = 0; it < 16; ++it) {
        int e = eb + it * 512 + t;
        int s = esrc[e] & 511;
        int d = edst[e] & 511;
        int p = atomicAdd(&wp[d], 1);
        g_cpack[eb + p] = s | (d << 16);
    }
}

// ---- Fused SGEMM via FFMA2 (round-8 form: 4x LDS.64 A + LDS.128 B + dup movs) ----
__global__ __launch_bounds__(256) void gemm_k(
    const float* __restrict__ Ax, int useH, int K,
    const float* __restrict__ Wl, const float* __restrict__ Wr)
{
    const float* A = useH ? g_H : Ax;
    __shared__ float As[16][132];   // [k][m]
    __shared__ float Bs[16][68];    // [k][n]
    int m0 = blockIdx.x * 128;
    int c0 = blockIdx.y * 64;
    const float* W = (c0 < 128) ? (Wl + c0) : (Wr + (c0 - 128));
    int t = threadIdx.x;
    int tx = t & 15;     // 16 x 4 cols
    int ty = t >> 4;     // 16 x 8 rows
    unsigned long long acc[4][4];
#pragma unroll
    for (int i = 0; i < 4; i++)
#pragma unroll
        for (int j = 0; j < 4; j++) acc[i][j] = 0ull;

    for (int k0 = 0; k0 < K; k0 += 16) {
#pragma unroll
        for (int r = 0; r < 2; ++r) {
            int idx = t + r * 256;
            int m = idx >> 2, k4 = idx & 3;
            float4 v = make_float4(0.f, 0.f, 0.f, 0.f);
            if (k0 + k4 * 4 < K)
                v = *(const float4*)&A[(m0 + m) * K + k0 + k4 * 4];
            As[k4 * 4 + 0][m] = v.x;
            As[k4 * 4 + 1][m] = v.y;
            As[k4 * 4 + 2][m] = v.z;
            As[k4 * 4 + 3][m] = v.w;
        }
        {
            int kk = t >> 4, n4 = t & 15;
            float4 v = make_float4(0.f, 0.f, 0.f, 0.f);
            if (k0 + kk < K)
                v = *(const float4*)&W[(k0 + kk) * HIDN + n4 * 4];
            *(float4*)&Bs[kk][n4 * 4] = v;
        }
        __syncthreads();
#pragma unroll
        for (int kk = 0; kk < 16; ++kk) {
            const float* ar = &As[kk][ty * 8];
            unsigned long long a0 = *(const unsigned long long*)(ar + 0);
            unsigned long long a1 = *(const unsigned long long*)(ar + 2);
            unsigned long long a2 = *(const unsigned long long*)(ar + 4);
            unsigned long long a3 = *(const unsigned long long*)(ar + 6);
            float4 b = *(const float4*)&Bs[kk][tx * 4];
            unsigned long long b0 = pk2(b.x, b.x);
            unsigned long long b1 = pk2(b.y, b.y);
            unsigned long long b2 = pk2(b.z, b.z);
            unsigned long long b3 = pk2(b.w, b.w);
            acc[0][0] = ffma2(a0, b0, acc[0][0]);
            acc[0][1] = ffma2(a0, b1, acc[0][1]);
            acc[0][2] = ffma2(a0, b2, acc[0][2]);
            acc[0][3] = ffma2(a0, b3, acc[0][3]);
            acc[1][0] = ffma2(a1, b0, acc[1][0]);
            acc[1][1] = ffma2(a1, b1, acc[1][1]);
            acc[1][2] = ffma2(a1, b2, acc[1][2]);
            acc[1][3] = ffma2(a1, b3, acc[1][3]);
            acc[2][0] = ffma2(a2, b0, acc[2][0]);
            acc[2][1] = ffma2(a2, b1, acc[2][1]);
            acc[2][2] = ffma2(a2, b2, acc[2][2]);
            acc[2][3] = ffma2(a2, b3, acc[2][3]);
            acc[3][0] = ffma2(a3, b0, acc[3][0]);
            acc[3][1] = ffma2(a3, b1, acc[3][1]);
            acc[3][2] = ffma2(a3, b2, acc[3][2]);
            acc[3][3] = ffma2(a3, b3, acc[3][3]);
        }
        __syncthreads();
    }
    int cbase = c0 + tx * 4;
    float* dstbase = (cbase < 128) ? g_XL : g_XR;
    int cc = cbase & 127;
    float* dst = dstbase + ((cc >> 5) * NN) * 32 + (cc & 31);
#pragma unroll
    for (int ip = 0; ip < 4; ip++) {
        float2 r0 = upk2(acc[ip][0]);
        float2 r1 = upk2(acc[ip][1]);
        float2 r2 = upk2(acc[ip][2]);
        float2 r3 = upk2(acc[ip][3]);
        int m = m0 + ty * 8 + ip * 2;
        *(float4*)&dst[m * 32] = make_float4(r0.x, r1.x, r2.x, r3.x);
        *(float4*)&dst[(m + 1) * 32] = make_float4(r0.y, r1.y, r2.y, r3.y);
    }
}

// ---- GATv2 attention: one block per (graph, head), 256 blocks = 1 wave @ 2/SM ----
// smem floats: xl 512*32 (XOR-swizzled 128B rows) + exp 8192 + src(u16) 4096 + att 32 + red 33
#define ATTN_FLOATS (16384 + 8192 + 4096 + 32 + 33)
#define ATTN_SMEM (ATTN_FLOATS * 4)

__global__ __launch_bounds__(512, 2) void attn_k(
    const float* __restrict__ att, const float* __restrict__ bias)
{
    extern __shared__ float sm[];
    float* s_xl  = sm;                        // [512][32] words, XOR-swizzled
    float* s_exp = sm + 16384;                // pd staging -> score -> exp
    unsigned short* s_src = (unsigned short*)(s_exp + 8192);
    float* s_att = (float*)(s_src + 8192);
    float* s_red = s_att + 32;

    int g = blockIdx.x >> 2;
    int head = blockIdx.x & 3;
    int t = threadIdx.x;
    int warp = t >> 5, lane = t & 31;
    int gn0 = g * 512;
    int ebase = g * 8192;

    // stage xl with XOR swizzle: word = n*32 + (d ^ ((n&7)*4)); float4-safe
    const float* XLg = g_XL + (head * NN + gn0) * 32;
    for (int i = t * 4; i < 16384; i += 2048) {
        int n = i >> 5, d = i & 31;
        int w = n * 32 + (d ^ ((n & 7) * 4));
        *(float4*)&s_xl[w] = *(const float4*)&XLg[i];
    }
    // stage packed edges (coalesced) into s_exp slots
    int* s_pd = (int*)s_exp;
#pragma unroll
    for (int it = 0; it < 16; ++it) {
        int e = it * 512 + t;
        s_pd[e] = g_cpack[ebase + e];
    }
    if (t < 32) s_att[t] = att[head * 32 + t];
    __syncthreads();

    // phase 1: thread owns 16 CONTIGUOUS edges (dst nearly constant -> xr reg-cached)
    const float* XRg = g_XR + (head * NN + gn0) * 32;
    float lmax = -3.4e38f;
    float4 xr[8];
    int curdst = -1;
    int ebeg = t * 16;
#pragma unroll 1
    for (int i = 0; i < 16; ++i) {
        int e = ebeg + i;
        int pd = s_pd[e];
        int srcl = pd & 511;
        int dstl = pd >> 16;
        if (dstl != curdst) {
            curdst = dstl;
            const float* xrp = XRg + dstl * 32;
#pragma unroll
            for (int q = 0; q < 8; ++q) xr[q] = *(const float4*)&xrp[q * 4];
        }
        const float* xlrow = s_xl + srcl * 32;
        int sx = (srcl & 7) * 4;
        float s = 0.f;
#pragma unroll
        for (int q = 0; q < 8; ++q) {
            float4 a = *(const float4*)&xlrow[(q * 4) ^ sx];
            float4 w4 = *(const float4*)&s_att[q * 4];
            float v;
            v = a.x + xr[q].x; v = fmaxf(v, 0.f) + NEG * fminf(v, 0.f); s = fmaf(v, w4.x, s);
            v = a.y + xr[q].y; v = fmaxf(v, 0.f) + NEG * fminf(v, 0.f); s = fmaf(v, w4.y, s);
            v = a.z + xr[q].z; v = fmaxf(v, 0.f) + NEG * fminf(v, 0.f); s = fmaf(v, w4.z, s);
            v = a.w + xr[q].w; v = fmaxf(v, 0.f) + NEG * fminf(v, 0.f); s = fmaf(v, w4.w, s);
        }
        s_exp[e] = s;                         // overwrite own pd slot
        s_src[e] = (unsigned short)srcl;
        lmax = fmaxf(lmax, s);
    }
    // block max (softmax shift-invariant; one shared shift is exact)
#pragma unroll
    for (int off = 16; off; off >>= 1)
        lmax = fmaxf(lmax, __shfl_xor_sync(0xffffffffu, lmax, off));
    if (lane == 0) s_red[warp] = lmax;
    __syncthreads();
    if (t == 0) {
        float m = s_red[0];
#pragma unroll
        for (int w = 1; w < 16; ++w) m = fmaxf(m, s_red[w]);
        s_red[16] = m;
    }
    __syncthreads();
    float mb = s_red[16];

    // phase 1b: edge-parallel exp in place
#pragma unroll
    for (int it = 0; it < 16; ++it) {
        int e = it * 512 + t;
        s_exp[e] = __expf(s_exp[e] - mb);
    }
    __syncthreads();

    // phase 2: warp = node, lane = dim; 16 warps x 32 iters = 512 nodes
    float bv = bias[head * 32 + lane];
    for (int it = 0; it < 32; ++it) {
        int nl = it * 16 + warp;
        int gn = gn0 + nl;
        int r0 = g_rp[gn] - ebase;
        int dg = g_deg[gn];
        float acc = 0.f, l = 0.f;
#pragma unroll 2
        for (int k = 0; k < dg; ++k) {
            int e = r0 + k;
            float a = s_exp[e];
            int srcl = s_src[e];
            l += a;
            acc = fmaf(a, s_xl[srcl * 32 + (lane ^ ((srcl & 7) * 4))], acc);
        }
        float h = fmaxf(acc * (1.f / fmaxf(l, 1e-16f)) + bv, 0.f);
        g_H[gn * 128 + head * 32 + lane] = h;
    }
}

// ---- readout: per-graph mean & max over 512 nodes (4-way chunked) ----
__global__ __launch_bounds__(512) void readout_k() {
    __shared__ float ssum[512];
    __shared__ float smx[512];
    int b = blockIdx.x, t = threadIdx.x;
    int c = t & 127, chunk = t >> 7;
    const float* Hp = g_H + (b * 512 + chunk * 128) * 128 + c;
    float sum = 0.f, mx = -3.4e38f;
    for (int n = 0; n < 128; ++n) {
        float v = Hp[n * 128];
        sum += v;
        mx = fmaxf(mx, v);
    }
    ssum[t] = sum;
    smx[t] = mx;
    __syncthreads();
    if (t < 128) {
        for (int k = 1; k < 4; ++k) {
            sum += ssum[t + 128 * k];
            mx = fmaxf(mx, smx[t + 128 * k]);
        }
        g_feat[b * 256 + t] = sum * (1.f / 512.f);
        g_feat[b * 256 + 128 + t] = mx;
    }
}

// ---- dueling head: one block per graph ----
__global__ __launch_bounds__(256) void head_k(
    const float* __restrict__ qW1, const float* __restrict__ qb1,
    const float* __restrict__ qW2, const float* __restrict__ qb2,
    const float* __restrict__ vW1, const float* __restrict__ vb1,
    const float* __restrict__ vW2, const float* __restrict__ vb2,
    float* __restrict__ out)
{
    __shared__ float sg[256];
    __shared__ float shq[128];
    __shared__ float shv[128];
    __shared__ float sred[256];
    int b = blockIdx.x, t = threadIdx.x;
    sg[t] = g_feat[b * 256 + t];
    __syncthreads();
    if (t < 128) {
        float a = qb1[t];
        for (int k = 0; k < 256; ++k) a = fmaf(sg[k], qW1[k * 128 + t], a);
        shq[t] = fmaxf(a, 0.f);
    } else {
        int c = t - 128;
        float a = vb1[c];
        for (int k = 0; k < 256; ++k) a = fmaf(sg[k], vW1[k * 128 + c], a);
        shv[c] = fmaxf(a, 0.f);
    }
    __syncthreads();
    float adv0 = qb2[t], adv1 = qb2[t + 256];
    for (int k = 0; k < 128; ++k) {
        float h = shq[k];
        adv0 = fmaf(h, qW2[k * 512 + t], adv0);
        adv1 = fmaf(h, qW2[k * 512 + t + 256], adv1);
    }
    sred[t] = (t < 128) ? shv[t] * vW2[t] : 0.f;
    __syncthreads();
    for (int s = 128; s > 0; s >>= 1) {
        if (t < s) sred[t] += sred[t + s];
        __syncthreads();
    }
    float val = sred[0] + vb2[0];
    __syncthreads();
    sred[t] = adv0 + adv1;
    __syncthreads();
    for (int s = 128; s > 0; s >>= 1) {
        if (t < s) sred[t] += sred[t + s];
        __syncthreads();
    }
    float mean = sred[0] * (1.f / 512.f);
    out[b * 512 + t] = val + adv0 - mean;
    out[b * 512 + t + 256] = val + adv1 - mean;
}

extern "C" void kernel_launch(void* const* d_in, const int* in_sizes, int n_in,
                              void* d_out, int out_size)
{
    (void)in_sizes; (void)n_in; (void)out_size;
    const float* x    = (const float*)d_in[0];
    const int*   esrc = (const int*)d_in[1];
    const int*   edst = (const int*)d_in[2];
    const float* Wl0  = (const float*)d_in[4];
    const float* Wr0  = (const float*)d_in[5];
    const float* att0 = (const float*)d_in[6];
    const float* b0   = (const float*)d_in[7];
    const float* Wl   = (const float*)d_in[8];
    const float* Wr   = (const float*)d_in[9];
    const float* attw = (const float*)d_in[10];
    const float* bw   = (const float*)d_in[11];
    const float* qW1  = (const float*)d_in[12];
    const float* qb1  = (const float*)d_in[13];
    const float* qW2  = (const float*)d_in[14];
    const float* qb2  = (const float*)d_in[15];
    const float* vW1  = (const float*)d_in[16];
    const float* vb1  = (const float*)d_in[17];
    const float* vW2  = (const float*)d_in[18];
    const float* vb2  = (const float*)d_in[19];
    float* out = (float*)d_out;

    cudaFuncSetAttribute(attn_k, cudaFuncAttributeMaxDynamicSharedMemorySize, ATTN_SMEM);

    // CSR build: single kernel, per-graph smem counting sort
    csr_build_k<<<BB, 512>>>(esrc, edst);

    // layer 0 (K=12)
    gemm_k<<<dim3(NN / 128, 4), 256>>>(x, 0, 12, Wl0, Wr0);
    attn_k<<<BB * NHEAD, 512, ATTN_SMEM>>>(att0, b0);

    // layers 1..3 (K=128)
    for (int i = 0; i < 3; ++i) {
        gemm_k<<<dim3(NN / 128, 4), 256>>>(nullptr, 1, 128,
                                           Wl + i * 128 * 128, Wr + i * 128 * 128);
        attn_k<<<BB * NHEAD, 512, ATTN_SMEM>>>(attw + i * 128, bw + i * 128);
    }

    readout_k<<<BB, 512>>>();
    head_k<<<BB, 256>>>(qW1, qb1, qW2, qb2, vW1, vb1, vW2, vb2, out);
}

// round 12
// speedup vs baseline: 1.1572x; 1.1572x over previous
#include <cuda_runtime.h>

#define NN   32768
#define EE   524288
#define BB   64
#define HIDN 128
#define NHEAD 4
#define DHEAD 32
#define NEG  0.2f
#define ECAP 4864   // per-half edge capacity (mean 4096, ~11 sigma slack)

// ---- scratch (static device memory; no allocation) ----
__device__ float g_XL[NHEAD * NN * DHEAD];   // [H][N][D]
__device__ float g_XR[NHEAD * NN * DHEAD];   // [H][N][D]
__device__ float g_H[NN * HIDN];             // node activations [N][128]
__device__ int   g_deg[NN];
__device__ int   g_rp[NN];
__device__ int   g_cpack[EE];                // srcLocal | dstLocal<<16, CSR-sorted by dst
__device__ float g_feat[BB * 2 * HIDN];      // [B][mean(128) | max(128)]

// ---- packed fp32x2 helpers ----
__device__ __forceinline__ unsigned long long pk2(float x, float y) {
    unsigned long long r;
    asm("mov.b64 %0, {%1, %2};" : "=l"(r) : "f"(x), "f"(y));
    return r;
}
__device__ __forceinline__ float2 upk2(unsigned long long v) {
    float2 r;
    asm("mov.b64 {%0, %1}, %2;" : "=f"(r.x), "=f"(r.y) : "l"(v));
    return r;
}
__device__ __forceinline__ unsigned long long ffma2(
    unsigned long long a, unsigned long long b, unsigned long long c) {
    unsigned long long d;
    asm("fma.rn.f32x2 %0, %1, %2, %3;" : "=l"(d) : "l"(a), "l"(b), "l"(c));
    return d;
}
__device__ __forceinline__ unsigned long long fadd2(
    unsigned long long a, unsigned long long b) {
    unsigned long long d;
    asm("add.rn.f32x2 %0, %1, %2;" : "=l"(d) : "l"(a), "l"(b));
    return d;
}
__device__ __forceinline__ unsigned long long fmul2(
    unsigned long long a, unsigned long long b) {
    unsigned long long d;
    asm("mul.rn.f32x2 %0, %1, %2;" : "=l"(d) : "l"(a), "l"(b));
    return d;
}

// ---- CSR build: one block per graph, counting sort entirely in smem ----
__global__ __launch_bounds__(512) void csr_build_k(
    const int* __restrict__ esrc, const int* __restrict__ edst)
{
    __shared__ int cnt[512];
    __shared__ int sc[512];
    __shared__ int wp[512];
    int g = blockIdx.x, t = threadIdx.x;
    int eb = g * 8192;
    cnt[t] = 0;
    __syncthreads();
#pragma unroll 1
    for (int it = 0; it < 16; ++it) {
        int d = edst[eb + it * 512 + t] & 511;
        atomicAdd(&cnt[d], 1);
    }
    __syncthreads();
    int d0 = cnt[t];
    int val = d0;
    sc[t] = val;
    __syncthreads();
    for (int off = 1; off < 512; off <<= 1) {
        int add = (t >= off) ? sc[t - off] : 0;
        __syncthreads();
        val += add;
        sc[t] = val;
        __syncthreads();
    }
    int rpx = val - d0;   // exclusive scan
    g_deg[g * 512 + t] = d0;
    g_rp[g * 512 + t] = eb + rpx;
    wp[t] = rpx;
    __syncthreads();
#pragma unroll 1
    for (int it = 0; it < 16; ++it) {
        int e = eb + it * 512 + t;
        int s = esrc[e] & 511;
        int d = edst[e] & 511;
        int p = atomicAdd(&wp[d], 1);
        g_cpack[eb + p] = s | (d << 16);
    }
}

// ---- Fused SGEMM via FFMA2 (round-8 form: 4x LDS.64 A + LDS.128 B + dup movs) ----
__global__ __launch_bounds__(256) void gemm_k(
    const float* __restrict__ Ax, int useH, int K,
    const float* __restrict__ Wl, const float* __restrict__ Wr)
{
    const float* A = useH ? g_H : Ax;
    __shared__ float As[16][132];   // [k][m]
    __shared__ float Bs[16][68];    // [k][n]
    int m0 = blockIdx.x * 128;
    int c0 = blockIdx.y * 64;
    const float* W = (c0 < 128) ? (Wl + c0) : (Wr + (c0 - 128));
    int t = threadIdx.x;
    int tx = t & 15;     // 16 x 4 cols
    int ty = t >> 4;     // 16 x 8 rows
    unsigned long long acc[4][4];
#pragma unroll
    for (int i = 0; i < 4; i++)
#pragma unroll
        for (int j = 0; j < 4; j++) acc[i][j] = 0ull;

    for (int k0 = 0; k0 < K; k0 += 16) {
#pragma unroll
        for (int r = 0; r < 2; ++r) {
            int idx = t + r * 256;
            int m = idx >> 2, k4 = idx & 3;
            float4 v = make_float4(0.f, 0.f, 0.f, 0.f);
            if (k0 + k4 * 4 < K)
                v = *(const float4*)&A[(m0 + m) * K + k0 + k4 * 4];
            As[k4 * 4 + 0][m] = v.x;
            As[k4 * 4 + 1][m] = v.y;
            As[k4 * 4 + 2][m] = v.z;
            As[k4 * 4 + 3][m] = v.w;
        }
        {
            int kk = t >> 4, n4 = t & 15;
            float4 v = make_float4(0.f, 0.f, 0.f, 0.f);
            if (k0 + kk < K)
                v = *(const float4*)&W[(k0 + kk) * HIDN + n4 * 4];
            *(float4*)&Bs[kk][n4 * 4] = v;
        }
        __syncthreads();
#pragma unroll
        for (int kk = 0; kk < 16; ++kk) {
            const float* ar = &As[kk][ty * 8];
            unsigned long long a0 = *(const unsigned long long*)(ar + 0);
            unsigned long long a1 = *(const unsigned long long*)(ar + 2);
            unsigned long long a2 = *(const unsigned long long*)(ar + 4);
            unsigned long long a3 = *(const unsigned long long*)(ar + 6);
            float4 b = *(const float4*)&Bs[kk][tx * 4];
            unsigned long long b0 = pk2(b.x, b.x);
            unsigned long long b1 = pk2(b.y, b.y);
            unsigned long long b2 = pk2(b.z, b.z);
            unsigned long long b3 = pk2(b.w, b.w);
            acc[0][0] = ffma2(a0, b0, acc[0][0]);
            acc[0][1] = ffma2(a0, b1, acc[0][1]);
            acc[0][2] = ffma2(a0, b2, acc[0][2]);
            acc[0][3] = ffma2(a0, b3, acc[0][3]);
            acc[1][0] = ffma2(a1, b0, acc[1][0]);
            acc[1][1] = ffma2(a1, b1, acc[1][1]);
            acc[1][2] = ffma2(a1, b2, acc[1][2]);
            acc[1][3] = ffma2(a1, b3, acc[1][3]);
            acc[2][0] = ffma2(a2, b0, acc[2][0]);
            acc[2][1] = ffma2(a2, b1, acc[2][1]);
            acc[2][2] = ffma2(a2, b2, acc[2][2]);
            acc[2][3] = ffma2(a2, b3, acc[2][3]);
            acc[3][0] = ffma2(a3, b0, acc[3][0]);
            acc[3][1] = ffma2(a3, b1, acc[3][1]);
            acc[3][2] = ffma2(a3, b2, acc[3][2]);
            acc[3][3] = ffma2(a3, b3, acc[3][3]);
        }
        __syncthreads();
    }
    int cbase = c0 + tx * 4;
    float* dstbase = (cbase < 128) ? g_XL : g_XR;
    int cc = cbase & 127;
    float* dst = dstbase + ((cc >> 5) * NN) * 32 + (cc & 31);
#pragma unroll
    for (int ip = 0; ip < 4; ip++) {
        float2 r0 = upk2(acc[ip][0]);
        float2 r1 = upk2(acc[ip][1]);
        float2 r2 = upk2(acc[ip][2]);
        float2 r3 = upk2(acc[ip][3]);
        int m = m0 + ty * 8 + ip * 2;
        *(float4*)&dst[m * 32] = make_float4(r0.x, r1.x, r2.x, r3.x);
        *(float4*)&dst[(m + 1) * 32] = make_float4(r0.y, r1.y, r2.y, r3.y);
    }
}

// ---- GATv2 attention per (graph, head, half): round-9 structure + packed scoring ----
// smem floats: xl 512*36 + ed 2*ECAP (interleaved (exp,src)) + wpack 32 + red 33
#define ATTN_FLOATS (512 * 36 + 2 * ECAP + 32 + 33)
#define ATTN_SMEM (ATTN_FLOATS * 4)

__global__ __launch_bounds__(512) void attn_k(
    const float* __restrict__ att, const float* __restrict__ bias)
{
    extern __shared__ float sm[];
    float*  s_xl  = sm;                       // stride 36 (16B-aligned rows)
    float2* s_ed  = (float2*)(sm + 512 * 36); // (score->exp, src-as-int-bits)
    unsigned long long* s_wp = (unsigned long long*)(sm + 512 * 36 + 2 * ECAP); // 16 packed w pairs
    float*  s_red = (float*)(s_wp + 16);

    int blk = blockIdx.x;
    int g = blk >> 3;
    int head = (blk >> 1) & 3;
    int half = blk & 1;
    int t = threadIdx.x;
    int warp = t >> 5, lane = t & 31;
    int gn0 = g * 512;
    int nh0 = half * 256;                    // local dst-node base
    int ebase = g * 8192;

    // stage full xl (gather source), vectorized
    const float* XLg = g_XL + (head * NN + gn0) * 32;
    for (int i = t * 4; i < 512 * 32; i += 2048) {
        int n = i >> 5, d = i & 31;
        *(float4*)&s_xl[n * 36 + d] = *(const float4*)&XLg[i];
    }
    if (t < 16) {
        float w0 = att[head * 32 + 2 * t];
        float w1 = att[head * 32 + 2 * t + 1];
        s_wp[t] = pk2(w0, w1);
    }

    // this half's edge span (CSR contiguous over dst)
    int e0 = g_rp[gn0 + nh0];
    int e1 = half ? (ebase + 8192) : g_rp[gn0 + 256];
    int ne = e1 - e0;
    if (ne > ECAP) ne = ECAP;   // unreachable (11-sigma), memory safety only
    __syncthreads();

    // phase 1: thread = edge; packed-f32x2 scoring.
    // lrelu(v) = 0.6v + 0.4|v| (exact for slope 0.2)
    const float* XRg = g_XR + (head * NN + gn0) * 32;
    const unsigned long long C06 = pk2(0.6f, 0.6f);
    const unsigned long long C04 = pk2(0.4f, 0.4f);
    const unsigned long long MABS = 0x7FFFFFFF7FFFFFFFull;
    float lmax = -3.4e38f;
#pragma unroll 1
    for (int e = t; e < ne; e += 512) {
        int pd = g_cpack[e0 + e];
        int srcl = pd & 511;
        int dstl = pd >> 16;
        const ulonglong2* xlp = (const ulonglong2*)(s_xl + srcl * 36);
        const float* xrp = XRg + dstl * 32;
        unsigned long long acca = 0ull, accb = 0ull;
#pragma unroll
        for (int q = 0; q < 8; ++q) {
            ulonglong2 a = xlp[q];                       // LDS.128: dims 4q..4q+3
            float4 bf = *(const float4*)&xrp[q * 4];     // LDG.128 (warp-broadcast)
            ulonglong2 b = *(ulonglong2*)&bf;            // register alias
            ulonglong2 wq = *(const ulonglong2*)&s_wp[q * 2]; // LDS.128: w pairs
            unsigned long long v0 = fadd2(a.x, b.x);
            unsigned long long v1 = fadd2(a.y, b.y);
            unsigned long long u0 = fmul2(v0, C06);
            unsigned long long u1 = fmul2(v1, C06);
            u0 = ffma2(v0 & MABS, C04, u0);
            u1 = ffma2(v1 & MABS, C04, u1);
            acca = ffma2(u0, wq.x, acca);
            accb = ffma2(u1, wq.y, accb);
        }
        float2 fa = upk2(acca);
        float2 fb = upk2(accb);
        float s = (fa.x + fa.y) + (fb.x + fb.y);
        s_ed[e] = make_float2(s, __int_as_float(srcl));
        lmax = fmaxf(lmax, s);
    }
    // block max (softmax shift-invariant; shared shift is exact per node)
#pragma unroll
    for (int off = 16; off; off >>= 1)
        lmax = fmaxf(lmax, __shfl_xor_sync(0xffffffffu, lmax, off));
    if (lane == 0) s_red[warp] = lmax;
    __syncthreads();
    if (t == 0) {
        float m = s_red[0];
#pragma unroll
        for (int w = 1; w < 16; ++w) m = fmaxf(m, s_red[w]);
        s_red[16] = m;
    }
    __syncthreads();
    float mb = s_red[16];

    // phase 1b: edge-parallel exp in place
#pragma unroll 1
    for (int e = t; e < ne; e += 512) {
        s_ed[e].x = __expf(s_ed[e].x - mb);
    }
    __syncthreads();

    // phase 2: warp = node, lane = dim; one LDS.64 broadcast per edge
    float bv = bias[head * 32 + lane];
    for (int it = 0; it < 16; ++it) {
        int nl = nh0 + it * 16 + warp;
        int gn = gn0 + nl;
        int r0 = g_rp[gn] - e0;
        int dg = g_deg[gn];
        float acc = 0.f, l = 0.f;
#pragma unroll 2
        for (int k = 0; k < dg; ++k) {
            float2 ed = s_ed[r0 + k];
            int srcl = __float_as_int(ed.y);
            l += ed.x;
            acc = fmaf(ed.x, s_xl[srcl * 36 + lane], acc);
        }
        float h = fmaxf(acc * (1.f / fmaxf(l, 1e-16f)) + bv, 0.f);
        g_H[gn * 128 + head * 32 + lane] = h;
    }
}

// ---- readout: per-graph mean & max over 512 nodes (4-way chunked) ----
__global__ __launch_bounds__(512) void readout_k() {
    __shared__ float ssum[512];
    __shared__ float smx[512];
    int b = blockIdx.x, t = threadIdx.x;
    int c = t & 127, chunk = t >> 7;
    const float* Hp = g_H + (b * 512 + chunk * 128) * 128 + c;
    float sum = 0.f, mx = -3.4e38f;
    for (int n = 0; n < 128; ++n) {
        float v = Hp[n * 128];
        sum += v;
        mx = fmaxf(mx, v);
    }
    ssum[t] = sum;
    smx[t] = mx;
    __syncthreads();
    if (t < 128) {
        for (int k = 1; k < 4; ++k) {
            sum += ssum[t + 128 * k];
            mx = fmaxf(mx, smx[t + 128 * k]);
        }
        g_feat[b * 256 + t] = sum * (1.f / 512.f);
        g_feat[b * 256 + 128 + t] = mx;
    }
}

// ---- dueling head: one block per graph ----
__global__ __launch_bounds__(256) void head_k(
    const float* __restrict__ qW1, const float* __restrict__ qb1,
    const float* __restrict__ qW2, const float* __restrict__ qb2,
    const float* __restrict__ vW1, const float* __restrict__ vb1,
    const float* __restrict__ vW2, const float* __restrict__ vb2,
    float* __restrict__ out)
{
    __shared__ float sg[256];
    __shared__ float shq[128];
    __shared__ float shv[128];
    __shared__ float sred[256];
    int b = blockIdx.x, t = threadIdx.x;
    sg[t] = g_feat[b * 256 + t];
    __syncthreads();
    if (t < 128) {
        float a = qb1[t];
        for (int k = 0; k < 256; ++k) a = fmaf(sg[k], qW1[k * 128 + t], a);
        shq[t] = fmaxf(a, 0.f);
    } else {
        int c = t - 128;
        float a = vb1[c];
        for (int k = 0; k < 256; ++k) a = fmaf(sg[k], vW1[k * 128 + c], a);
        shv[c] = fmaxf(a, 0.f);
    }
    __syncthreads();
    float adv0 = qb2[t], adv1 = qb2[t + 256];
    for (int k = 0; k < 128; ++k) {
        float h = shq[k];
        adv0 = fmaf(h, qW2[k * 512 + t], adv0);
        adv1 = fmaf(h, qW2[k * 512 + t + 256], adv1);
    }
    sred[t] = (t < 128) ? shv[t] * vW2[t] : 0.f;
    __syncthreads();
    for (int s = 128; s > 0; s >>= 1) {
        if (t < s) sred[t] += sred[t + s];
        __syncthreads();
    }
    float val = sred[0] + vb2[0];
    __syncthreads();
    sred[t] = adv0 + adv1;
    __syncthreads();
    for (int s = 128; s > 0; s >>= 1) {
        if (t < s) sred[t] += sred[t + s];
        __syncthreads();
    }
    float mean = sred[0] * (1.f / 512.f);
    out[b * 512 + t] = val + adv0 - mean;
    out[b * 512 + t + 256] = val + adv1 - mean;
}

extern "C" void kernel_launch(void* const* d_in, const int* in_sizes, int n_in,
                              void* d_out, int out_size)
{
    (void)in_sizes; (void)n_in; (void)out_size;
    const float* x    = (const float*)d_in[0];
    const int*   esrc = (const int*)d_in[1];
    const int*   edst = (const int*)d_in[2];
    const float* Wl0  = (const float*)d_in[4];
    const float* Wr0  = (const float*)d_in[5];
    const float* att0 = (const float*)d_in[6];
    const float* b0   = (const float*)d_in[7];
    const float* Wl   = (const float*)d_in[8];
    const float* Wr   = (const float*)d_in[9];
    const float* attw = (const float*)d_in[10];
    const float* bw   = (const float*)d_in[11];
    const float* qW1  = (const float*)d_in[12];
    const float* qb1  = (const float*)d_in[13];
    const float* qW2  = (const float*)d_in[14];
    const float* qb2  = (const float*)d_in[15];
    const float* vW1  = (const float*)d_in[16];
    const float* vb1  = (const float*)d_in[17];
    const float* vW2  = (const float*)d_in[18];
    const float* vb2  = (const float*)d_in[19];
    float* out = (float*)d_out;

    cudaFuncSetAttribute(attn_k, cudaFuncAttributeMaxDynamicSharedMemorySize, ATTN_SMEM);

    // CSR build: single kernel, per-graph smem counting sort
    csr_build_k<<<BB, 512>>>(esrc, edst);

    // layer 0 (K=12)
    gemm_k<<<dim3(NN / 128, 4), 256>>>(x, 0, 12, Wl0, Wr0);
    attn_k<<<BB * NHEAD * 2, 512, ATTN_SMEM>>>(att0, b0);

    // layers 1..3 (K=128)
    for (int i = 0; i < 3; ++i) {
        gemm_k<<<dim3(NN / 128, 4), 256>>>(nullptr, 1, 128,
                                           Wl + i * 128 * 128, Wr + i * 128 * 128);
        attn_k<<<BB * NHEAD * 2, 512, ATTN_SMEM>>>(attw + i * 128, bw + i * 128);
    }

    readout_k<<<BB, 512>>>();
    head_k<<<BB, 256>>>(qW1, qb1, qW2, qb2, vW1, vb1, vW2, vb2, out);
}